// round 5
// baseline (speedup 1.0000x reference)
#include <cuda_runtime.h>
#include <cuda_bf16.h>
#include <cstdint>

// ============================ device scratch ============================
#define MAX_B 8192
__device__ float g_pooled[MAX_B * 128];
__device__ int   g_cumsum[MAX_B];
// s8 weight limb images Wt[n][k]: [layer][limb][128*144]
__device__ __align__(16) signed char g_wimg8[4][2][128 * 144];

// ============================ constants ============================
#define RN       128
#define TILE_M   128
#define THREADS  256

#define KB1      112    // byte stride, K=96 region used (7*16: conflict-free ldsm)
#define KSTEPS1  3
#define KB2      144    // byte stride, K=128 used (9*16)
#define KSTEPS2  4
#define I2ST     132    // f32 stride for RR overlay

#define HX_SZ    (128 * KB1)            // 14336 per limb
#define AC_SZ    (128 * KB2)            // 18432 per limb
#define OFF_HX0  0
#define OFF_HX1  HX_SZ                  // 14336
#define OFF_AC0  (2 * HX_SZ)            // 28672
#define OFF_AC1  (OFF_AC0 + AC_SZ)      // 47104
#define OFF_WA   (OFF_AC1 + AC_SZ)      // 65536
#define OFF_WB   (OFF_WA + 2 * AC_SZ)   // 102400
#define OFF_BIAS (OFF_WB + 2 * AC_SZ)   // 139264 : 4*128 f32
#define OFF_GIDX (OFF_BIAS + 2048)      // 141312 : 128 ints
#define OFF_MASK (OFF_GIDX + 512)       // 141824 : 128 f32
#define SMEM_SZ  (OFF_MASK + 512)       // 142336
// RR overlay [0, 128*132*4=67584) covers HX+ACT+2KB of WA (dead by then)

// dequant scales: sA * sW * 2^-21
#define SC_L1 4.76837158203125e-7f      // sA=8,  sW=1/8  -> 2^-21
#define SC_I2 1.1920928955078125e-7f    // sA=2,  sW=1/8  -> 2^-23
#define SC_J2 4.76837158203125e-7f      // sA=8,  sW=1/8  -> 2^-21

// ============================ ptx helpers ============================
__device__ __forceinline__ uint32_t smem_u32(const void* p) {
    uint32_t a;
    asm("{ .reg .u64 t; cvta.to.shared.u64 t, %1; cvt.u32.u64 %0, t; }" : "=r"(a) : "l"(p));
    return a;
}
__device__ __forceinline__ void ldsm4(uint32_t r[4], uint32_t a) {
    asm volatile("ldmatrix.sync.aligned.m8n8.x4.shared.b16 {%0,%1,%2,%3}, [%4];"
                 : "=r"(r[0]), "=r"(r[1]), "=r"(r[2]), "=r"(r[3]) : "r"(a));
}
__device__ __forceinline__ void mma_s8(int c[4], const uint32_t a[4], uint32_t b0, uint32_t b1) {
    asm volatile(
        "mma.sync.aligned.m16n8k32.row.col.s32.s8.s8.s32 "
        "{%0,%1,%2,%3}, {%4,%5,%6,%7}, {%8,%9}, {%0,%1,%2,%3};"
        : "+r"(c[0]), "+r"(c[1]), "+r"(c[2]), "+r"(c[3])
        : "r"(a[0]), "r"(a[1]), "r"(a[2]), "r"(a[3]), "r"(b0), "r"(b1));
}
__device__ __forceinline__ void cp16(uint32_t dst, const void* src) {
    asm volatile("cp.async.cg.shared.global [%0], [%1], 16;" :: "r"(dst), "l"(src));
}
#define CP_COMMIT() asm volatile("cp.async.commit_group;" ::: "memory")
#define CP_WAIT0()  asm volatile("cp.async.wait_group 0;" ::: "memory")

// ============================ math helpers ============================
__device__ __forceinline__ float fast_ex2(float x) { float r; asm("ex2.approx.ftz.f32 %0, %1;" : "=f"(r) : "f"(x)); return r; }
__device__ __forceinline__ float fast_rcp(float x) { float r; asm("rcp.approx.ftz.f32 %0, %1;" : "=f"(r) : "f"(x)); return r; }
#define L2E 1.4426950408889634f
__device__ __forceinline__ float sigmoid_f(float x) { return fast_rcp(1.0f + fast_ex2(-x * L2E)); }
__device__ __forceinline__ float tanh_f(float x)    { return 1.0f - 2.0f * fast_rcp(1.0f + fast_ex2(2.0f * x * L2E)); }
__device__ __forceinline__ float selu_f(float x) {
    float e = fast_ex2(x * L2E);
    float neg = 1.6732632423543772f * (e - 1.0f);
    return 1.0507009873554805f * ((x > 0.0f) ? x : neg);
}

// quantize a' (pre-scaled to ~(-1,1)) into two s8 limbs: a' ~= q0/128 + q1/16384
__device__ __forceinline__ void qlimbs(float ap, int& q0, int& q1) {
    float s = fminf(fmaxf(ap, -0.9921875f), 0.9921875f);
    int A0 = __float2int_rn(s * 128.0f);
    float resid = fmaf((float)A0, -0.0078125f, s);
    int A1 = __float2int_rn(resid * 16384.0f);
    q0 = A0; q1 = A1;
}
__device__ __forceinline__ uint32_t pk4(int a, int b, int c, int d) {
    return (uint32_t)(a & 0xff) | ((uint32_t)(b & 0xff) << 8) |
           ((uint32_t)(c & 0xff) << 16) | ((uint32_t)(d & 0xff) << 24);
}
__device__ __forceinline__ uint16_t pk2(int a, int b) {
    return (uint16_t)((a & 0xff) | ((b & 0xff) << 8));
}

// ============================ prologue kernels ============================
__global__ void scan_kernel(const int* __restrict__ nn, int B) {
    __shared__ int s[1024];
    int tid = threadIdx.x;
    int per = (B + 1023) >> 10;
    if (per > 8) per = 8;
    int base = tid * per;
    int loc[8];
    int sum = 0;
    for (int e = 0; e < per; e++) {
        int idx = base + e;
        int v = (idx < B) ? nn[idx] : 0;
        loc[e] = v; sum += v;
    }
    s[tid] = sum;
    __syncthreads();
    for (int off = 1; off < 1024; off <<= 1) {
        int v = (tid >= off) ? s[tid - off] : 0;
        __syncthreads();
        s[tid] += v;
        __syncthreads();
    }
    int run = s[tid] - sum;
    for (int e = 0; e < per; e++) {
        int idx = base + e;
        if (idx < B) { run += loc[e]; g_cumsum[idx] = run; }
    }
}

__global__ void zero_kernel(int count) {
    int i = blockIdx.x * blockDim.x + threadIdx.x;
    if (i < count) g_pooled[i] = 0.0f;
}

// Wt[n][k] = W[k][n] / sW, two s8 limbs; zero-pad k in [kact, kpad)
__global__ void quant_w_kernel(const float* __restrict__ w, int kact, int kpad, int KB, int layer) {
    int idx = blockIdx.x * blockDim.x + threadIdx.x;
    if (idx >= 128 * kpad) return;
    int n = idx / kpad, k = idx - n * kpad;
    float v = (k < kact) ? w[k * 128 + n] : 0.0f;
    int q0, q1;
    qlimbs(v * 8.0f, q0, q1);              // / sW, sW = 1/8
    g_wimg8[layer][0][n * KB + k] = (signed char)q0;
    g_wimg8[layer][1][n * KB + k] = (signed char)q1;
}

// ============================ gemm pieces ============================
__device__ __forceinline__ void prefetch_w(uint32_t sb, uint32_t dstOff, int layer, int limbBytes) {
#pragma unroll
    for (int limb = 0; limb < 2; limb++) {
        const char* src = (const char*)&g_wimg8[layer][limb][0];
        uint32_t dst = sb + dstOff + (uint32_t)(limb * limbBytes);
        int n16 = limbBytes >> 4;
        for (int i = threadIdx.x; i < n16; i += THREADS)
            cp16(dst + (uint32_t)(i * 16), src + i * 16);
    }
    CP_COMMIT();
}

__device__ __forceinline__ void zero_acc(int acc[2][8][4]) {
#pragma unroll
    for (int a = 0; a < 2; a++)
#pragma unroll
        for (int b = 0; b < 8; b++)
#pragma unroll
            for (int c = 0; c < 4; c++) acc[a][b][c] = 0;
}
__device__ __forceinline__ void shl7(int acc[2][8][4]) {
#pragma unroll
    for (int a = 0; a < 2; a++)
#pragma unroll
        for (int b = 0; b < 8; b++)
#pragma unroll
            for (int c = 0; c < 4; c++) acc[a][b][c] <<= 7;
}

// sweep 1: acc += A0 * W0
template <int KSTEPS, int KB>
__device__ __forceinline__ void sweep_s1(uint32_t aB, uint32_t wB, int acc[2][8][4],
                                         int wm, int wn, int lane) {
    uint32_t aAddr = aB + (uint32_t)((wm * 32 + (lane & 15)) * KB + 16 * (lane >> 4));
    uint32_t bAddr = wB + (uint32_t)((wn * 64 + (lane & 7) + 8 * (lane >> 4)) * KB
                                     + 16 * ((lane >> 3) & 1));
#pragma unroll
    for (int ks = 0; ks < KSTEPS; ks++) {
        uint32_t a0[4], a1[4], b[4][4];
        ldsm4(a0, aAddr);
        ldsm4(a1, aAddr + 16 * KB);
#pragma unroll
        for (int g = 0; g < 4; g++) ldsm4(b[g], bAddr + g * (16 * KB));
        aAddr += 32; bAddr += 32;
#pragma unroll
        for (int g = 0; g < 4; g++) {
            mma_s8(acc[0][2 * g],     a0, b[g][0], b[g][1]);
            mma_s8(acc[0][2 * g + 1], a0, b[g][2], b[g][3]);
            mma_s8(acc[1][2 * g],     a1, b[g][0], b[g][1]);
            mma_s8(acc[1][2 * g + 1], a1, b[g][2], b[g][3]);
        }
    }
}

// sweep 2: acc += A0 * W1 + A1 * W0
template <int KSTEPS, int KB>
__device__ __forceinline__ void sweep_s2(uint32_t a0B, uint32_t a1B, uint32_t w0B, uint32_t w1B,
                                         int acc[2][8][4], int wm, int wn, int lane) {
    uint32_t aOff = (uint32_t)((wm * 32 + (lane & 15)) * KB + 16 * (lane >> 4));
    uint32_t bOff = (uint32_t)((wn * 64 + (lane & 7) + 8 * (lane >> 4)) * KB
                               + 16 * ((lane >> 3) & 1));
    uint32_t aA0 = a0B + aOff, aA1 = a1B + aOff;
    uint32_t bW0 = w0B + bOff, bW1 = w1B + bOff;
#pragma unroll
    for (int ks = 0; ks < KSTEPS; ks++) {
        uint32_t a0[4], a1[4], c0[4], c1[4], b0g[4][4], b1g[4][4];
        ldsm4(a0, aA0); ldsm4(a1, aA0 + 16 * KB);
        ldsm4(c0, aA1); ldsm4(c1, aA1 + 16 * KB);
#pragma unroll
        for (int g = 0; g < 4; g++) {
            ldsm4(b1g[g], bW1 + g * (16 * KB));
            ldsm4(b0g[g], bW0 + g * (16 * KB));
        }
        aA0 += 32; aA1 += 32; bW0 += 32; bW1 += 32;
#pragma unroll
        for (int g = 0; g < 4; g++) {
            mma_s8(acc[0][2 * g],     a0, b1g[g][0], b1g[g][1]);
            mma_s8(acc[0][2 * g + 1], a0, b1g[g][2], b1g[g][3]);
            mma_s8(acc[1][2 * g],     a1, b1g[g][0], b1g[g][1]);
            mma_s8(acc[1][2 * g + 1], a1, b1g[g][2], b1g[g][3]);
            mma_s8(acc[0][2 * g],     c0, b0g[g][0], b0g[g][1]);
            mma_s8(acc[0][2 * g + 1], c0, b0g[g][2], b0g[g][3]);
            mma_s8(acc[1][2 * g],     c1, b0g[g][0], b0g[g][1]);
            mma_s8(acc[1][2 * g + 1], c1, b0g[g][2], b0g[g][3]);
        }
    }
}

// dequant + bias + activation + requantize into act limb tiles
// ACT 1 = tanh (qs = 0.5, sA=2), ACT 2 = selu (qs = 0.125, sA=8)
template <int ACT>
__device__ __forceinline__ void epi_act(int acc[2][8][4], char* sm, int biasIdx,
                                        float sc, float qs, int wm, int wn, int lane) {
    const float* bias = (const float*)(sm + OFF_BIAS) + biasIdx * 128;
    char* a0B = sm + OFF_AC0;
    char* a1B = sm + OFF_AC1;
    int mb = wm * 32 + (lane >> 2);
#pragma unroll
    for (int nt = 0; nt < 8; nt++) {
        int n = wn * 64 + nt * 8 + 2 * (lane & 3);
        float2 bv = *(const float2*)&bias[n];
#pragma unroll
        for (int mt = 0; mt < 2; mt++)
#pragma unroll
            for (int half = 0; half < 2; half++) {
                int m = mb + mt * 16 + half * 8;
                float x0 = (float)acc[mt][nt][2 * half]     * sc + bv.x;
                float x1 = (float)acc[mt][nt][2 * half + 1] * sc + bv.y;
                x0 = (ACT == 1) ? tanh_f(x0) : selu_f(x0);
                x1 = (ACT == 1) ? tanh_f(x1) : selu_f(x1);
                int q0a, q1a, q0b, q1b;
                qlimbs(x0 * qs, q0a, q1a);
                qlimbs(x1 * qs, q0b, q1b);
                *(uint16_t*)(a0B + m * KB2 + n) = pk2(q0a, q0b);
                *(uint16_t*)(a1B + m * KB2 + n) = pk2(q1a, q1b);
            }
    }
}

// ============================ fused main kernel ============================
__global__ void __launch_bounds__(THREADS, 1)
fused_kernel(const float* __restrict__ nodes, const float* __restrict__ nmask,
             const float* __restrict__ i1b, const float* __restrict__ i2b,
             const float* __restrict__ j1b, const float* __restrict__ j2b,
             int N, int B) {
    extern __shared__ char sm[];
    uint32_t sb = smem_u32(sm);
    int tid = threadIdx.x;
    int lane = tid & 31, wid = tid >> 5;
    int wm = wid & 3, wn = wid >> 2;

    float* biasS = (float*)(sm + OFF_BIAS);
    int*   gidxS = (int*)(sm + OFF_GIDX);
    float* maskS = (float*)(sm + OFF_MASK);

    // kick off Wi1 (both limbs) -> WA; overlap with hx quantize
    prefetch_w(sb, OFF_WA, 0, HX_SZ);

    for (int i = tid; i < 512; i += THREADS) {
        const float* bp = (i < 128) ? i1b : (i < 256) ? i2b : (i < 384) ? j1b : j2b;
        biasS[i] = bp[i & 127];
    }
    if (tid < 128) {
        int gn = blockIdx.x * TILE_M + tid;
        maskS[tid] = (gn < N) ? nmask[gn] : 0.0f;
        int lo = 0, hi = B - 1;
        while (lo < hi) {
            int mid = (lo + hi) >> 1;
            if (gn < g_cumsum[mid]) hi = mid; else lo = mid + 1;
        }
        gidxS[tid] = lo;
    }

    // ---- load + quantize hx tile [128 rows x 96 k-bytes], two limbs ----
    {
        int m = tid & 127, h = tid >> 7;
        int gn = blockIdx.x * TILE_M + m;
        char* h0 = sm + OFF_HX0;
        char* h1 = sm + OFF_HX1;
        float xv[32];
        if (gn < N) {
#pragma unroll
            for (int q = 0; q < 8; q++)
                ((float4*)xv)[q] = *(const float4*)&nodes[(size_t)gn * 64 + h * 32 + q * 4];
        } else {
#pragma unroll
            for (int i = 0; i < 32; i++) xv[i] = 0.0f;
        }
        int q0[32], q1[32];
#pragma unroll
        for (int i = 0; i < 32; i++) qlimbs(xv[i] * 0.125f, q0[i], q1[i]);  // sA = 8
        uint32_t w0[8], w1[8];
#pragma unroll
        for (int p = 0; p < 8; p++) {
            w0[p] = pk4(q0[4 * p], q0[4 * p + 1], q0[4 * p + 2], q0[4 * p + 3]);
            w1[p] = pk4(q1[4 * p], q1[4 * p + 1], q1[4 * p + 2], q1[4 * p + 3]);
        }
        int base = m * KB1 + h * 32;
        *(uint4*)(h0 + base)      = make_uint4(w0[0], w0[1], w0[2], w0[3]);
        *(uint4*)(h0 + base + 16) = make_uint4(w0[4], w0[5], w0[6], w0[7]);
        *(uint4*)(h1 + base)      = make_uint4(w1[0], w1[1], w1[2], w1[3]);
        *(uint4*)(h1 + base + 16) = make_uint4(w1[4], w1[5], w1[6], w1[7]);
        if (h == 1) {
            // k 64..95: first-two coords re-appended, then zeros
            float e0 = 0.0f, e1 = 0.0f;
            if (gn < N) { e0 = nodes[(size_t)gn * 64]; e1 = nodes[(size_t)gn * 64 + 1]; }
            int a0, a1b, c0, c1b;
            qlimbs(e0 * 0.125f, a0, c0);
            qlimbs(e1 * 0.125f, a1b, c1b);
            int base2 = m * KB1 + 64;
            *(uint4*)(h0 + base2)      = make_uint4(pk4(a0, a1b, 0, 0), 0u, 0u, 0u);
            *(uint4*)(h0 + base2 + 16) = make_uint4(0u, 0u, 0u, 0u);
            *(uint4*)(h1 + base2)      = make_uint4(pk4(c0, c1b, 0, 0), 0u, 0u, 0u);
            *(uint4*)(h1 + base2 + 16) = make_uint4(0u, 0u, 0u, 0u);
        }
    }

    uint32_t hx0 = sb + OFF_HX0, hx1 = sb + OFF_HX1;
    uint32_t ac0 = sb + OFF_AC0, ac1 = sb + OFF_AC1;
    uint32_t wA = sb + OFF_WA, wB_ = sb + OFF_WB;

    CP_WAIT0();
    __syncthreads();

    int acc[2][8][4];
    float ri[2][8][4];

    // ===== G1: i layer-1 (WA = Wi1) =====
    prefetch_w(sb, OFF_WB, 1, AC_SZ);                 // Wi2 -> WB
    zero_acc(acc);
    sweep_s1<KSTEPS1, KB1>(hx0, wA, acc, wm, wn, lane);
    shl7(acc);
    sweep_s2<KSTEPS1, KB1>(hx0, hx1, wA, wA + HX_SZ, acc, wm, wn, lane);
    epi_act<1>(acc, sm, 0, SC_L1, 0.5f, wm, wn, lane);
    CP_WAIT0(); __syncthreads();

    // ===== G2: i layer-2 (WB = Wi2) -> registers =====
    prefetch_w(sb, OFF_WA, 2, HX_SZ);                 // Wj1 -> WA
    zero_acc(acc);
    sweep_s1<KSTEPS2, KB2>(ac0, wB_, acc, wm, wn, lane);
    shl7(acc);
    sweep_s2<KSTEPS2, KB2>(ac0, ac1, wB_, wB_ + AC_SZ, acc, wm, wn, lane);
    {
        const float* bias = biasS + 1 * 128;
#pragma unroll
        for (int nt = 0; nt < 8; nt++) {
            int n = wn * 64 + nt * 8 + 2 * (lane & 3);
            float2 bv = *(const float2*)&bias[n];
#pragma unroll
            for (int mt = 0; mt < 2; mt++) {
                ri[mt][nt][0] = (float)acc[mt][nt][0] * SC_I2 + bv.x;
                ri[mt][nt][1] = (float)acc[mt][nt][1] * SC_I2 + bv.y;
                ri[mt][nt][2] = (float)acc[mt][nt][2] * SC_I2 + bv.x;
                ri[mt][nt][3] = (float)acc[mt][nt][3] * SC_I2 + bv.y;
            }
        }
    }
    CP_WAIT0(); __syncthreads();

    // ===== G3: j layer-1 (WA = Wj1) =====
    prefetch_w(sb, OFF_WB, 3, AC_SZ);                 // Wj2 -> WB
    zero_acc(acc);
    sweep_s1<KSTEPS1, KB1>(hx0, wA, acc, wm, wn, lane);
    shl7(acc);
    sweep_s2<KSTEPS1, KB1>(hx0, hx1, wA, wA + HX_SZ, acc, wm, wn, lane);
    __syncthreads();                                   // G2 act reads done before overwrite
    epi_act<2>(acc, sm, 2, SC_L1, 0.125f, wm, wn, lane);
    CP_WAIT0(); __syncthreads();

    // ===== G4: j layer-2 (WB = Wj2) =====
    zero_acc(acc);
    sweep_s1<KSTEPS2, KB2>(ac0, wB_, acc, wm, wn, lane);
    shl7(acc);
    sweep_s2<KSTEPS2, KB2>(ac0, ac1, wB_, wB_ + AC_SZ, acc, wm, wn, lane);
    __syncthreads();                                   // act reads done before RR overlay

    // ---- gate: RR = sigmoid(i2) * (j2+bias) * mask, overlay at sm+0 ----
    {
        const float* bias = biasS + 3 * 128;
        float* RR = (float*)sm;
        int mb = wm * 32 + (lane >> 2);
#pragma unroll
        for (int nt = 0; nt < 8; nt++) {
            int n = wn * 64 + nt * 8 + 2 * (lane & 3);
            float2 bv = *(const float2*)&bias[n];
#pragma unroll
            for (int mt = 0; mt < 2; mt++)
#pragma unroll
                for (int half = 0; half < 2; half++) {
                    int m = mb + mt * 16 + half * 8;
                    float mk = maskS[m];
                    float2 o;
                    o.x = sigmoid_f(ri[mt][nt][2 * half])
                          * ((float)acc[mt][nt][2 * half] * SC_J2 + bv.x) * mk;
                    o.y = sigmoid_f(ri[mt][nt][2 * half + 1])
                          * ((float)acc[mt][nt][2 * half + 1] * SC_J2 + bv.y) * mk;
                    *(float2*)&RR[m * I2ST + n] = o;
                }
        }
    }
    __syncthreads();

    // ---- segmented column sum -> atomicAdd ----
    {
        const float* RR = (const float*)sm;
        int c = tid & 127;
        int h = tid >> 7;
        int m0 = h * 64;
        float cs = 0.0f;
        int gcur = gidxS[m0];
        for (int mm = m0; mm < m0 + 64; mm++) {
            float r = RR[mm * I2ST + c];
            int g = gidxS[mm];
            if (g != gcur) { atomicAdd(&g_pooled[gcur * RN + c], cs); cs = 0.0f; gcur = g; }
            cs += r;
        }
        atomicAdd(&g_pooled[gcur * RN + c], cs);
    }
}

// ============================ final per-graph MLP ============================
__global__ void final_kernel(const float* __restrict__ h1w, const float* __restrict__ h1b,
                             const float* __restrict__ h2w, const float* __restrict__ h2b,
                             float* __restrict__ out, int B) {
    int g = blockIdx.x * (blockDim.x >> 5) + (threadIdx.x >> 5);
    int lane = threadIdx.x & 31;
    if (g >= B) return;
    const float* pr = &g_pooled[g * RN];
    float4 bv = ((const float4*)h1b)[lane];
    float a0 = bv.x, a1 = bv.y, a2 = bv.z, a3 = bv.w;
#pragma unroll 4
    for (int k = 0; k < RN; k++) {
        float pv = pr[k];
        float4 wv = *(const float4*)(h1w + k * RN + (lane << 2));
        a0 = fmaf(pv, wv.x, a0);
        a1 = fmaf(pv, wv.y, a1);
        a2 = fmaf(pv, wv.z, a2);
        a3 = fmaf(pv, wv.w, a3);
    }
    a0 = selu_f(a0); a1 = selu_f(a1); a2 = selu_f(a2); a3 = selu_f(a3);
    float4 h2 = ((const float4*)h2w)[lane];
    float part = a0 * h2.x + a1 * h2.y + a2 * h2.z + a3 * h2.w;
#pragma unroll
    for (int off = 16; off > 0; off >>= 1)
        part += __shfl_down_sync(0xffffffffu, part, off);
    if (lane == 0) out[g] = part + h2b[0];
}

// ============================ launch ============================
extern "C" void kernel_launch(void* const* d_in, const int* in_sizes, int n_in,
                              void* d_out, int out_size) {
    const float* nodes = (const float*)d_in[0];
    const float* nmask = (const float*)d_in[1];
    const int*   n_node = (const int*)d_in[2];
    const float* i1w = (const float*)d_in[3];
    const float* i1b = (const float*)d_in[4];
    const float* i2w = (const float*)d_in[5];
    const float* i2b = (const float*)d_in[6];
    const float* j1w = (const float*)d_in[7];
    const float* j1b = (const float*)d_in[8];
    const float* j2w = (const float*)d_in[9];
    const float* j2b = (const float*)d_in[10];
    const float* h1w = (const float*)d_in[11];
    const float* h1b = (const float*)d_in[12];
    const float* h2w = (const float*)d_in[13];
    const float* h2b = (const float*)d_in[14];

    int N = in_sizes[1];
    int B = in_sizes[2];

    scan_kernel<<<1, 1024>>>(n_node, B);

    int pc = B * RN;
    zero_kernel<<<(pc + 255) / 256, 256>>>(pc);

    // layers: 0=i1 (K96), 1=i2 (K128), 2=j1 (K96), 3=j2 (K128)
    quant_w_kernel<<<(128 * 96 + 255) / 256, 256>>>(i1w, 66, 96, KB1, 0);
    quant_w_kernel<<<(128 * 128 + 255) / 256, 256>>>(i2w, 128, 128, KB2, 1);
    quant_w_kernel<<<(128 * 96 + 255) / 256, 256>>>(j1w, 66, 96, KB1, 2);
    quant_w_kernel<<<(128 * 128 + 255) / 256, 256>>>(j2w, 128, 128, KB2, 3);

    cudaFuncSetAttribute(fused_kernel, cudaFuncAttributeMaxDynamicSharedMemorySize, SMEM_SZ);
    int grid = (N + TILE_M - 1) / TILE_M;
    fused_kernel<<<grid, THREADS, SMEM_SZ>>>(nodes, nmask, i1b, i2b, j1b, j2b, N, B);

    final_kernel<<<(B + 7) / 8, 256>>>(h1w, h1b, h2w, h2b, (float*)d_out, B);
}

// round 6
// speedup vs baseline: 3.1844x; 3.1844x over previous
#include <cuda_runtime.h>
#include <cuda_fp16.h>
#include <cstdint>

// ============================ device scratch ============================
#define MAX_B 8192
__device__ float g_pooled[MAX_B * 128];
__device__ int   g_cumsum[MAX_B];
// f16 weight images Wt[n][k] (single limb): [layer][128*136]
__device__ __align__(16) __half g_wimg[4][128 * 136];

// ============================ constants ============================
#define RN       128
#define TILE_M   128
#define THREADS  256

#define KST1     72     // f16 element stride, K=64 tiles (144B rows: conflict-free ldsm)
#define KSTEPS1  4
#define KST2     136    // K=128 tiles (272B rows)
#define KSTEPS2  8
#define I2ST     132    // f32 stride for RR overlay

#define HX_HALF  (128 * KST1 * 2)            // 18432
#define OFF_HX   0                            // hi+lo = 36864
#define ACT_HALF (128 * KST2 * 2)            // 34816
#define OFF_ACT  (2 * HX_HALF)               // 36864 ; hi+lo = 69632
#define OFF_W0   (OFF_ACT + 2 * ACT_HALF)    // 106496 (35KB buffer)
#define OFF_W1   (OFF_W0 + ACT_HALF)         // 141312 (35KB buffer)
#define OFF_BIAS (OFF_W1 + ACT_HALF)         // 176128 : 4*128 f32
#define OFF_GIDX (OFF_BIAS + 2048)           // 178176 : 128 ints
#define OFF_MASK (OFF_GIDX + 512)            // 178688 : 128 f32
#define SMEM_SZ  (OFF_MASK + 512)            // 179200
// RR overlay [0, 128*132*4 = 67584) over hx+act(part) — both dead by gate time

// ============================ ptx helpers ============================
__device__ __forceinline__ uint32_t smem_u32(const void* p) {
    uint32_t a;
    asm("{ .reg .u64 t; cvta.to.shared.u64 t, %1; cvt.u32.u64 %0, t; }" : "=r"(a) : "l"(p));
    return a;
}
__device__ __forceinline__ void ldsm4(uint32_t r[4], uint32_t a) {
    asm volatile("ldmatrix.sync.aligned.m8n8.x4.shared.b16 {%0,%1,%2,%3}, [%4];"
                 : "=r"(r[0]), "=r"(r[1]), "=r"(r[2]), "=r"(r[3]) : "r"(a));
}
__device__ __forceinline__ void mma16816(float c[4], const uint32_t a[4], uint32_t b0, uint32_t b1) {
    asm volatile(
        "mma.sync.aligned.m16n8k16.row.col.f32.f16.f16.f32 "
        "{%0,%1,%2,%3}, {%4,%5,%6,%7}, {%8,%9}, {%0,%1,%2,%3};"
        : "+f"(c[0]), "+f"(c[1]), "+f"(c[2]), "+f"(c[3])
        : "r"(a[0]), "r"(a[1]), "r"(a[2]), "r"(a[3]), "r"(b0), "r"(b1));
}
__device__ __forceinline__ void cp16(uint32_t dst, const void* src) {
    asm volatile("cp.async.cg.shared.global [%0], [%1], 16;" :: "r"(dst), "l"(src));
}
#define CP_COMMIT() asm volatile("cp.async.commit_group;" ::: "memory")
#define CP_WAIT0()  asm volatile("cp.async.wait_group 0;" ::: "memory")

// ============================ math helpers ============================
__device__ __forceinline__ float fast_ex2(float x) { float r; asm("ex2.approx.ftz.f32 %0, %1;" : "=f"(r) : "f"(x)); return r; }
__device__ __forceinline__ float fast_rcp(float x) { float r; asm("rcp.approx.ftz.f32 %0, %1;" : "=f"(r) : "f"(x)); return r; }
#define L2E 1.4426950408889634f
__device__ __forceinline__ float sigmoid_f(float x) { return fast_rcp(1.0f + fast_ex2(-x * L2E)); }
__device__ __forceinline__ float tanh_f(float x)    { return 1.0f - 2.0f * fast_rcp(1.0f + fast_ex2(2.0f * x * L2E)); }
__device__ __forceinline__ float selu_f(float x) {
    float e = fast_ex2(x * L2E);
    float neg = 1.6732632423543772f * (e - 1.0f);
    return 1.0507009873554805f * ((x > 0.0f) ? x : neg);
}

// pack two f32 -> f16x2 (e0 low, e1 high)
__device__ __forceinline__ uint32_t pkh2(float e0, float e1) {
    uint32_t r; asm("cvt.rn.f16x2.f32 %0, %1, %2;" : "=r"(r) : "f"(e1), "f"(e0)); return r;
}
// hi/lo f16 split of a pair; returns hi word and lo word
__device__ __forceinline__ void qsplit2(float e0, float e1, uint32_t& hw, uint32_t& lw) {
    hw = pkh2(e0, e1);
    float f0 = __half2float(__ushort_as_half((unsigned short)(hw & 0xffffu)));
    float f1 = __half2float(__ushort_as_half((unsigned short)(hw >> 16)));
    lw = pkh2(e0 - f0, e1 - f1);
}

// ============================ prologue kernels ============================
__global__ void scan_kernel(const int* __restrict__ nn, int B) {
    __shared__ int s[1024];
    int tid = threadIdx.x;
    int per = (B + 1023) >> 10;
    if (per > 8) per = 8;
    int base = tid * per;
    int loc[8];
    int sum = 0;
    for (int e = 0; e < per; e++) {
        int idx = base + e;
        int v = (idx < B) ? nn[idx] : 0;
        loc[e] = v; sum += v;
    }
    s[tid] = sum;
    __syncthreads();
    for (int off = 1; off < 1024; off <<= 1) {
        int v = (tid >= off) ? s[tid - off] : 0;
        __syncthreads();
        s[tid] += v;
        __syncthreads();
    }
    int run = s[tid] - sum;
    for (int e = 0; e < per; e++) {
        int idx = base + e;
        if (idx < B) { run += loc[e]; g_cumsum[idx] = run; }
    }
}

__global__ void zero_kernel(int count) {
    int i = blockIdx.x * blockDim.x + threadIdx.x;
    if (i < count) g_pooled[i] = 0.0f;
}

// layer-1 weights with exact coord fold: W'[k][n] = W[k][n] + (k<2 ? W[64+k][n] : 0), K=64
__global__ void quant_w1_kernel(const float* __restrict__ w, int layer) {
    int idx = blockIdx.x * blockDim.x + threadIdx.x;
    if (idx >= 128 * 64) return;
    int n = idx >> 6, k = idx & 63;
    float v = w[k * 128 + n];
    if (k < 2) v += w[(64 + k) * 128 + n];
    g_wimg[layer][n * KST1 + k] = __float2half(v);
}
// layer-2 weights: Wt[n][k] = W[k][n], K=128
__global__ void quant_w2_kernel(const float* __restrict__ w, int layer) {
    int idx = blockIdx.x * blockDim.x + threadIdx.x;
    if (idx >= 128 * 128) return;
    int n = idx >> 7, k = idx & 127;
    g_wimg[layer][n * KST2 + k] = __float2half(w[k * 128 + n]);
}

// ============================ gemm pieces ============================
__device__ __forceinline__ void prefetch_w(uint32_t sb, uint32_t dstOff, int layer, int bytes) {
    const char* src = (const char*)&g_wimg[layer][0];
    uint32_t dst = sb + dstOff;
    int n16 = bytes >> 4;
    for (int i = threadIdx.x; i < n16; i += THREADS)
        cp16(dst + (uint32_t)(i * 16), src + i * 16);
    CP_COMMIT();
}

__device__ __forceinline__ void zero_acc(float acc[2][8][4]) {
#pragma unroll
    for (int a = 0; a < 2; a++)
#pragma unroll
        for (int b = 0; b < 8; b++)
#pragma unroll
            for (int c = 0; c < 4; c++) acc[a][b][c] = 0.0f;
}

// merged 2-pass: (Ah + Al) * W, sharing B fragments per k-step
template <int KSTEPS, int KST>
__device__ __forceinline__ void gemm_pass12(uint32_t aHi, uint32_t aLo, uint32_t wBase,
                                            float acc[2][8][4], int wm, int wn, int lane) {
    uint32_t aOff = (uint32_t)(((wm * 32 + (lane & 15)) * KST + 8 * (lane >> 4)) * 2);
    uint32_t aH = aHi + aOff, aL = aLo + aOff;
    uint32_t bAddr = wBase + (uint32_t)(((wn * 64 + (lane & 7) + 8 * (lane >> 4)) * KST
                                         + 8 * ((lane >> 3) & 1)) * 2);
#pragma unroll
    for (int ks = 0; ks < KSTEPS; ks++) {
        uint32_t b[4][4];
#pragma unroll
        for (int g = 0; g < 4; g++) ldsm4(b[g], bAddr + g * (16 * KST * 2));
        bAddr += 32;
        uint32_t a0[4], a1[4];
        ldsm4(a0, aH); ldsm4(a1, aH + 16 * KST * 2); aH += 32;
#pragma unroll
        for (int g = 0; g < 4; g++) {
            mma16816(acc[0][2 * g],     a0, b[g][0], b[g][1]);
            mma16816(acc[0][2 * g + 1], a0, b[g][2], b[g][3]);
            mma16816(acc[1][2 * g],     a1, b[g][0], b[g][1]);
            mma16816(acc[1][2 * g + 1], a1, b[g][2], b[g][3]);
        }
        ldsm4(a0, aL); ldsm4(a1, aL + 16 * KST * 2); aL += 32;
#pragma unroll
        for (int g = 0; g < 4; g++) {
            mma16816(acc[0][2 * g],     a0, b[g][0], b[g][1]);
            mma16816(acc[0][2 * g + 1], a0, b[g][2], b[g][3]);
            mma16816(acc[1][2 * g],     a1, b[g][0], b[g][1]);
            mma16816(acc[1][2 * g + 1], a1, b[g][2], b[g][3]);
        }
    }
}

// ACT 1 = tanh, 2 = selu: bias + act + f16 hi/lo requantize into act tile
template <int ACT>
__device__ __forceinline__ void epilogue_act(float acc[2][8][4], char* sm, int biasIdx,
                                             int wm, int wn, int lane) {
    const float* bias = (const float*)(sm + OFF_BIAS) + biasIdx * 128;
    char* hiB = sm + OFF_ACT;
    char* loB = hiB + ACT_HALF;
    int mb = wm * 32 + (lane >> 2);
#pragma unroll
    for (int nt = 0; nt < 8; nt++) {
        int n = wn * 64 + nt * 8 + 2 * (lane & 3);
        float2 bv = *(const float2*)&bias[n];
#pragma unroll
        for (int mt = 0; mt < 2; mt++)
#pragma unroll
            for (int half = 0; half < 2; half++) {
                int m = mb + mt * 16 + half * 8;
                float x0 = acc[mt][nt][2 * half]     + bv.x;
                float x1 = acc[mt][nt][2 * half + 1] + bv.y;
                x0 = (ACT == 1) ? tanh_f(x0) : selu_f(x0);
                x1 = (ACT == 1) ? tanh_f(x1) : selu_f(x1);
                uint32_t hw, lw;
                qsplit2(x0, x1, hw, lw);
                int off = (m * KST2 + n) * 2;
                *(uint32_t*)(hiB + off) = hw;
                *(uint32_t*)(loB + off) = lw;
            }
    }
}

// ============================ fused main kernel ============================
__global__ void __launch_bounds__(THREADS, 1)
fused_kernel(const float* __restrict__ nodes, const float* __restrict__ nmask,
             const float* __restrict__ i1b, const float* __restrict__ i2b,
             const float* __restrict__ j1b, const float* __restrict__ j2b,
             int N, int B) {
    extern __shared__ char sm[];
    uint32_t sb = smem_u32(sm);
    int tid = threadIdx.x;
    int lane = tid & 31, wid = tid >> 5;
    int wm = wid & 3, wn = wid >> 2;

    float* biasS = (float*)(sm + OFF_BIAS);
    int*   gidxS = (int*)(sm + OFF_GIDX);
    float* maskS = (float*)(sm + OFF_MASK);

    // kick off Wi1' -> W0; overlap with hx quantize
    prefetch_w(sb, OFF_W0, 0, HX_HALF);

    for (int i = tid; i < 512; i += THREADS) {
        const float* bp = (i < 128) ? i1b : (i < 256) ? i2b : (i < 384) ? j1b : j2b;
        biasS[i] = bp[i & 127];
    }
    if (tid < 128) {
        int gn = blockIdx.x * TILE_M + tid;
        maskS[tid] = (gn < N) ? nmask[gn] : 0.0f;
        int lo = 0, hi = B - 1;
        while (lo < hi) {
            int mid = (lo + hi) >> 1;
            if (gn < g_cumsum[mid]) hi = mid; else lo = mid + 1;
        }
        gidxS[tid] = lo;
    }

    // ---- load + quantize x tile [128 x 64] (f16 hi/lo); K-fold makes extra coords unnecessary ----
    {
        int m = tid & 127, h = tid >> 7;
        int gn = blockIdx.x * TILE_M + m;
        char* hiB = sm + OFF_HX;
        char* loB = hiB + HX_HALF;
        float xv[32];
        if (gn < N) {
#pragma unroll
            for (int q = 0; q < 8; q++)
                ((float4*)xv)[q] = *(const float4*)&nodes[(size_t)gn * 64 + h * 32 + q * 4];
        } else {
#pragma unroll
            for (int i = 0; i < 32; i++) xv[i] = 0.0f;
        }
        uint32_t hw[16], lw[16];
#pragma unroll
        for (int p = 0; p < 16; p++)
            qsplit2(xv[2 * p], xv[2 * p + 1], hw[p], lw[p]);
        int base = m * (KST1 * 2) + h * 64;   // bytes; both 16B-aligned
#pragma unroll
        for (int q = 0; q < 4; q++) {
            *(uint4*)(hiB + base + q * 16) = ((uint4*)hw)[q];
            *(uint4*)(loB + base + q * 16) = ((uint4*)lw)[q];
        }
    }

    uint32_t hxHi = sb + OFF_HX, hxLo = hxHi + HX_HALF;
    uint32_t acHi = sb + OFF_ACT, acLo = acHi + ACT_HALF;
    uint32_t w0 = sb + OFF_W0, w1 = sb + OFF_W1;

    CP_WAIT0();
    __syncthreads();

    float acc[2][8][4];
    float ri[2][8][4];   // i2 output (+bias) kept in registers

    // ===== G1: i layer-1 (W0 = Wi1') =====
    prefetch_w(sb, OFF_W1, 1, ACT_HALF);               // Wi2 -> W1
    zero_acc(acc);
    gemm_pass12<KSTEPS1, KST1>(hxHi, hxLo, w0, acc, wm, wn, lane);
    epilogue_act<1>(acc, sm, 0, wm, wn, lane);
    CP_WAIT0(); __syncthreads();

    // ===== G2: i layer-2 (W1 = Wi2) -> registers =====
    prefetch_w(sb, OFF_W0, 2, HX_HALF);                // Wj1' -> W0
    zero_acc(acc);
    gemm_pass12<KSTEPS2, KST2>(acHi, acLo, w1, acc, wm, wn, lane);
    {
        const float* bias = biasS + 1 * 128;
#pragma unroll
        for (int nt = 0; nt < 8; nt++) {
            int n = wn * 64 + nt * 8 + 2 * (lane & 3);
            float2 bv = *(const float2*)&bias[n];
#pragma unroll
            for (int mt = 0; mt < 2; mt++) {
                ri[mt][nt][0] = acc[mt][nt][0] + bv.x;
                ri[mt][nt][1] = acc[mt][nt][1] + bv.y;
                ri[mt][nt][2] = acc[mt][nt][2] + bv.x;
                ri[mt][nt][3] = acc[mt][nt][3] + bv.y;
            }
        }
    }
    CP_WAIT0(); __syncthreads();

    // ===== G3: j layer-1 (W0 = Wj1') =====
    prefetch_w(sb, OFF_W1, 3, ACT_HALF);               // Wj2 -> W1
    zero_acc(acc);
    gemm_pass12<KSTEPS1, KST1>(hxHi, hxLo, w0, acc, wm, wn, lane);
    epilogue_act<2>(acc, sm, 2, wm, wn, lane);         // act reads from G2 done (post-sync)
    CP_WAIT0(); __syncthreads();

    // ===== G4: j layer-2 (W1 = Wj2) =====
    zero_acc(acc);
    gemm_pass12<KSTEPS2, KST2>(acHi, acLo, w1, acc, wm, wn, lane);
    __syncthreads();   // all act reads done before RR overlay

    // ---- gate: RR = sigmoid(i2) * (j2 + bias) * mask, overlay at sm+0 ----
    {
        const float* bias = biasS + 3 * 128;
        float* RR = (float*)sm;
        int mb = wm * 32 + (lane >> 2);
#pragma unroll
        for (int nt = 0; nt < 8; nt++) {
            int n = wn * 64 + nt * 8 + 2 * (lane & 3);
            float2 bv = *(const float2*)&bias[n];
#pragma unroll
            for (int mt = 0; mt < 2; mt++)
#pragma unroll
                for (int half = 0; half < 2; half++) {
                    int m = mb + mt * 16 + half * 8;
                    float mk = maskS[m];
                    float2 o;
                    o.x = sigmoid_f(ri[mt][nt][2 * half])
                          * (acc[mt][nt][2 * half] + bv.x) * mk;
                    o.y = sigmoid_f(ri[mt][nt][2 * half + 1])
                          * (acc[mt][nt][2 * half + 1] + bv.y) * mk;
                    *(float2*)&RR[m * I2ST + n] = o;
                }
        }
    }
    __syncthreads();

    // ---- segmented column sum -> atomicAdd ----
    {
        const float* RR = (const float*)sm;
        int c = tid & 127;
        int h = tid >> 7;
        int m0 = h * 64;
        float cs = 0.0f;
        int gcur = gidxS[m0];
        for (int mm = m0; mm < m0 + 64; mm++) {
            float r = RR[mm * I2ST + c];
            int g = gidxS[mm];
            if (g != gcur) { atomicAdd(&g_pooled[gcur * RN + c], cs); cs = 0.0f; gcur = g; }
            cs += r;
        }
        atomicAdd(&g_pooled[gcur * RN + c], cs);
    }
}

// ============================ final per-graph MLP ============================
__global__ void final_kernel(const float* __restrict__ h1w, const float* __restrict__ h1b,
                             const float* __restrict__ h2w, const float* __restrict__ h2b,
                             float* __restrict__ out, int B) {
    int g = blockIdx.x * (blockDim.x >> 5) + (threadIdx.x >> 5);
    int lane = threadIdx.x & 31;
    if (g >= B) return;
    const float* pr = &g_pooled[g * RN];
    float4 bv = ((const float4*)h1b)[lane];
    float a0 = bv.x, a1 = bv.y, a2 = bv.z, a3 = bv.w;
#pragma unroll 4
    for (int k = 0; k < RN; k++) {
        float pv = pr[k];
        float4 wv = *(const float4*)(h1w + k * RN + (lane << 2));
        a0 = fmaf(pv, wv.x, a0);
        a1 = fmaf(pv, wv.y, a1);
        a2 = fmaf(pv, wv.z, a2);
        a3 = fmaf(pv, wv.w, a3);
    }
    a0 = selu_f(a0); a1 = selu_f(a1); a2 = selu_f(a2); a3 = selu_f(a3);
    float4 h2 = ((const float4*)h2w)[lane];
    float part = a0 * h2.x + a1 * h2.y + a2 * h2.z + a3 * h2.w;
#pragma unroll
    for (int off = 16; off > 0; off >>= 1)
        part += __shfl_down_sync(0xffffffffu, part, off);
    if (lane == 0) out[g] = part + h2b[0];
}

// ============================ launch ============================
extern "C" void kernel_launch(void* const* d_in, const int* in_sizes, int n_in,
                              void* d_out, int out_size) {
    const float* nodes = (const float*)d_in[0];
    const float* nmask = (const float*)d_in[1];
    const int*   n_node = (const int*)d_in[2];
    const float* i1w = (const float*)d_in[3];
    const float* i1b = (const float*)d_in[4];
    const float* i2w = (const float*)d_in[5];
    const float* i2b = (const float*)d_in[6];
    const float* j1w = (const float*)d_in[7];
    const float* j1b = (const float*)d_in[8];
    const float* j2w = (const float*)d_in[9];
    const float* j2b = (const float*)d_in[10];
    const float* h1w = (const float*)d_in[11];
    const float* h1b = (const float*)d_in[12];
    const float* h2w = (const float*)d_in[13];
    const float* h2b = (const float*)d_in[14];

    int N = in_sizes[1];
    int B = in_sizes[2];

    scan_kernel<<<1, 1024>>>(n_node, B);

    int pc = B * RN;
    zero_kernel<<<(pc + 255) / 256, 256>>>(pc);

    // layers: 0=i1' (K64, folded), 1=i2 (K128), 2=j1' (K64, folded), 3=j2 (K128)
    quant_w1_kernel<<<(128 * 64 + 255) / 256, 256>>>(i1w, 0);
    quant_w2_kernel<<<(128 * 128 + 255) / 256, 256>>>(i2w, 1);
    quant_w1_kernel<<<(128 * 64 + 255) / 256, 256>>>(j1w, 2);
    quant_w2_kernel<<<(128 * 128 + 255) / 256, 256>>>(j2w, 3);

    cudaFuncSetAttribute(fused_kernel, cudaFuncAttributeMaxDynamicSharedMemorySize, SMEM_SZ);
    int grid = (N + TILE_M - 1) / TILE_M;
    fused_kernel<<<grid, THREADS, SMEM_SZ>>>(nodes, nmask, i1b, i2b, j1b, j2b, N, B);

    final_kernel<<<(B + 7) / 8, 256>>>(h1w, h1b, h2w, h2b, (float*)d_out, B);
}

// round 7
// speedup vs baseline: 3.9138x; 1.2291x over previous
#include <cuda_runtime.h>
#include <cuda_fp16.h>
#include <cstdint>

// ============================ device scratch ============================
#define MAX_B 8192
__device__ float g_pooled[MAX_B * 128];
__device__ int   g_cumsum[MAX_B];
// f16 weight images Wt[n][k]: [layer][128*136]
__device__ __align__(16) __half g_wimg[4][128 * 136];

// ============================ constants ============================
#define RN       128
#define TILE_M   64
#define THREADS  256

#define KST1     72     // f16 stride, K=64 (144B rows, conflict-free ldsm)
#define KSTEPS1  4
#define KST2     136    // K=128 (272B rows)
#define KSTEPS2  8
#define I2ST     132

#define HX_HALF  (TILE_M * KST1 * 2)          // 9216
#define OFF_HX   0                             // hi+lo = 18432
#define ACT_HALF (TILE_M * KST2 * 2)          // 17408
#define OFF_ACT  (2 * HX_HALF)                // 18432 ; hi+lo = 34816 (RR overlays)
#define W1_BYTES (128 * KST1 * 2)             // 18432
#define W2_BYTES (128 * KST2 * 2)             // 34816
#define OFF_WL1  (OFF_ACT + 2 * ACT_HALF)     // 53248
#define OFF_WL2  (OFF_WL1 + W1_BYTES)         // 71680
#define OFF_BIAS (OFF_WL2 + W2_BYTES)         // 106496 : 4*128 f32
#define OFF_GIDX (OFF_BIAS + 2048)            // 108544 : 64 ints
#define OFF_MASK (OFF_GIDX + 256)             // 108800 : 64 f32
#define SMEM_SZ  (OFF_MASK + 256)             // 109056  (x2 = 218KB/SM -> 2 CTAs)

// ============================ ptx helpers ============================
__device__ __forceinline__ uint32_t smem_u32(const void* p) {
    uint32_t a;
    asm("{ .reg .u64 t; cvta.to.shared.u64 t, %1; cvt.u32.u64 %0, t; }" : "=r"(a) : "l"(p));
    return a;
}
__device__ __forceinline__ void ldsm4(uint32_t r[4], uint32_t a) {
    asm volatile("ldmatrix.sync.aligned.m8n8.x4.shared.b16 {%0,%1,%2,%3}, [%4];"
                 : "=r"(r[0]), "=r"(r[1]), "=r"(r[2]), "=r"(r[3]) : "r"(a));
}
__device__ __forceinline__ void mma16816(float c[4], const uint32_t a[4], uint32_t b0, uint32_t b1) {
    asm volatile(
        "mma.sync.aligned.m16n8k16.row.col.f32.f16.f16.f32 "
        "{%0,%1,%2,%3}, {%4,%5,%6,%7}, {%8,%9}, {%0,%1,%2,%3};"
        : "+f"(c[0]), "+f"(c[1]), "+f"(c[2]), "+f"(c[3])
        : "r"(a[0]), "r"(a[1]), "r"(a[2]), "r"(a[3]), "r"(b0), "r"(b1));
}
__device__ __forceinline__ void cp16(uint32_t dst, const void* src) {
    asm volatile("cp.async.cg.shared.global [%0], [%1], 16;" :: "r"(dst), "l"(src));
}
#define CP_COMMIT() asm volatile("cp.async.commit_group;" ::: "memory")
#define CP_WAIT0()  asm volatile("cp.async.wait_group 0;" ::: "memory")

// ============================ math helpers ============================
__device__ __forceinline__ float fast_ex2(float x) { float r; asm("ex2.approx.ftz.f32 %0, %1;" : "=f"(r) : "f"(x)); return r; }
__device__ __forceinline__ float fast_rcp(float x) { float r; asm("rcp.approx.ftz.f32 %0, %1;" : "=f"(r) : "f"(x)); return r; }
#define L2E 1.4426950408889634f
__device__ __forceinline__ float sigmoid_f(float x) { return fast_rcp(1.0f + fast_ex2(-x * L2E)); }
__device__ __forceinline__ float tanh_f(float x)    { return 1.0f - 2.0f * fast_rcp(1.0f + fast_ex2(2.0f * x * L2E)); }
__device__ __forceinline__ float selu_f(float x) {
    float e = fast_ex2(x * L2E);
    float neg = 1.6732632423543772f * (e - 1.0f);
    return 1.0507009873554805f * ((x > 0.0f) ? x : neg);
}
__device__ __forceinline__ uint32_t pkh2(float e0, float e1) {
    uint32_t r; asm("cvt.rn.f16x2.f32 %0, %1, %2;" : "=r"(r) : "f"(e1), "f"(e0)); return r;
}
__device__ __forceinline__ void qsplit2(float e0, float e1, uint32_t& hw, uint32_t& lw) {
    hw = pkh2(e0, e1);
    float f0 = __half2float(__ushort_as_half((unsigned short)(hw & 0xffffu)));
    float f1 = __half2float(__ushort_as_half((unsigned short)(hw >> 16)));
    lw = pkh2(e0 - f0, e1 - f1);
}

// ============================ prologue kernels ============================
__global__ void scan_kernel(const int* __restrict__ nn, int B) {
    __shared__ int s[1024];
    int tid = threadIdx.x;
    int per = (B + 1023) >> 10;
    if (per > 8) per = 8;
    int base = tid * per;
    int loc[8];
    int sum = 0;
    for (int e = 0; e < per; e++) {
        int idx = base + e;
        int v = (idx < B) ? nn[idx] : 0;
        loc[e] = v; sum += v;
    }
    s[tid] = sum;
    __syncthreads();
    for (int off = 1; off < 1024; off <<= 1) {
        int v = (tid >= off) ? s[tid - off] : 0;
        __syncthreads();
        s[tid] += v;
        __syncthreads();
    }
    int run = s[tid] - sum;
    for (int e = 0; e < per; e++) {
        int idx = base + e;
        if (idx < B) { run += loc[e]; g_cumsum[idx] = run; }
    }
}

__global__ void zero_kernel(int count) {
    int i = blockIdx.x * blockDim.x + threadIdx.x;
    if (i < count) g_pooled[i] = 0.0f;
}

// layer-1 weights with exact coord fold: W'[k][n] = W[k][n] + (k<2 ? W[64+k][n] : 0), K=64
__global__ void quant_w1_kernel(const float* __restrict__ w, int layer) {
    int idx = blockIdx.x * blockDim.x + threadIdx.x;
    if (idx >= 128 * 64) return;
    int n = idx >> 6, k = idx & 63;
    float v = w[k * 128 + n];
    if (k < 2) v += w[(64 + k) * 128 + n];
    g_wimg[layer][n * KST1 + k] = __float2half(v);
}
__global__ void quant_w2_kernel(const float* __restrict__ w, int layer) {
    int idx = blockIdx.x * blockDim.x + threadIdx.x;
    if (idx >= 128 * 128) return;
    int n = idx >> 7, k = idx & 127;
    g_wimg[layer][n * KST2 + k] = __float2half(w[k * 128 + n]);
}

// ============================ gemm pieces ============================
__device__ __forceinline__ void prefetch_w(uint32_t sb, uint32_t dstOff, int layer, int bytes) {
    const char* src = (const char*)&g_wimg[layer][0];
    uint32_t dst = sb + dstOff;
    int n16 = bytes >> 4;
    for (int i = threadIdx.x; i < n16; i += THREADS)
        cp16(dst + (uint32_t)(i * 16), src + i * 16);
    CP_COMMIT();
}

__device__ __forceinline__ void zero_acc(float acc[2][4][4]) {
#pragma unroll
    for (int a = 0; a < 2; a++)
#pragma unroll
        for (int b = 0; b < 4; b++)
#pragma unroll
            for (int c = 0; c < 4; c++) acc[a][b][c] = 0.0f;
}

// merged 2-pass: (Ah + Al) * W, warp covers 32 rows x 32 cols
template <int KSTEPS, int KST>
__device__ __forceinline__ void gemm_pass12(uint32_t aHi, uint32_t aLo, uint32_t wBase,
                                            float acc[2][4][4], int wm, int wn, int lane) {
    uint32_t aOff = (uint32_t)(((wm * 32 + (lane & 15)) * KST + 8 * (lane >> 4)) * 2);
    uint32_t aH = aHi + aOff, aL = aLo + aOff;
    uint32_t bAddr = wBase + (uint32_t)(((wn * 32 + (lane & 7) + 8 * (lane >> 4)) * KST
                                         + 8 * ((lane >> 3) & 1)) * 2);
#pragma unroll
    for (int ks = 0; ks < KSTEPS; ks++) {
        uint32_t b[2][4];
#pragma unroll
        for (int g = 0; g < 2; g++) ldsm4(b[g], bAddr + g * (16 * KST * 2));
        bAddr += 32;
        uint32_t a0[4], a1[4];
        ldsm4(a0, aH); ldsm4(a1, aH + 16 * KST * 2); aH += 32;
#pragma unroll
        for (int g = 0; g < 2; g++) {
            mma16816(acc[0][2 * g],     a0, b[g][0], b[g][1]);
            mma16816(acc[0][2 * g + 1], a0, b[g][2], b[g][3]);
            mma16816(acc[1][2 * g],     a1, b[g][0], b[g][1]);
            mma16816(acc[1][2 * g + 1], a1, b[g][2], b[g][3]);
        }
        ldsm4(a0, aL); ldsm4(a1, aL + 16 * KST * 2); aL += 32;
#pragma unroll
        for (int g = 0; g < 2; g++) {
            mma16816(acc[0][2 * g],     a0, b[g][0], b[g][1]);
            mma16816(acc[0][2 * g + 1], a0, b[g][2], b[g][3]);
            mma16816(acc[1][2 * g],     a1, b[g][0], b[g][1]);
            mma16816(acc[1][2 * g + 1], a1, b[g][2], b[g][3]);
        }
    }
}

// ACT 1 = tanh, 2 = selu
template <int ACT>
__device__ __forceinline__ void epilogue_act(float acc[2][4][4], char* sm, int biasIdx,
                                             int wm, int wn, int lane) {
    const float* bias = (const float*)(sm + OFF_BIAS) + biasIdx * 128;
    char* hiB = sm + OFF_ACT;
    char* loB = hiB + ACT_HALF;
    int mb = wm * 32 + (lane >> 2);
#pragma unroll
    for (int nt = 0; nt < 4; nt++) {
        int n = wn * 32 + nt * 8 + 2 * (lane & 3);
        float2 bv = *(const float2*)&bias[n];
#pragma unroll
        for (int mt = 0; mt < 2; mt++)
#pragma unroll
            for (int half = 0; half < 2; half++) {
                int m = mb + mt * 16 + half * 8;
                float x0 = acc[mt][nt][2 * half]     + bv.x;
                float x1 = acc[mt][nt][2 * half + 1] + bv.y;
                x0 = (ACT == 1) ? tanh_f(x0) : selu_f(x0);
                x1 = (ACT == 1) ? tanh_f(x1) : selu_f(x1);
                uint32_t hw, lw;
                qsplit2(x0, x1, hw, lw);
                int off = (m * KST2 + n) * 2;
                *(uint32_t*)(hiB + off) = hw;
                *(uint32_t*)(loB + off) = lw;
            }
    }
}

// ============================ fused main kernel ============================
__global__ void __launch_bounds__(THREADS, 2)
fused_kernel(const float* __restrict__ nodes, const float* __restrict__ nmask,
             const float* __restrict__ i1b, const float* __restrict__ i2b,
             const float* __restrict__ j1b, const float* __restrict__ j2b,
             int N, int B) {
    extern __shared__ char sm[];
    uint32_t sb = smem_u32(sm);
    int tid = threadIdx.x;
    int lane = tid & 31, wid = tid >> 5;
    int wm = wid & 1, wn = wid >> 1;     // 2 x 4 warp grid: 32 rows x 32 cols each

    float* biasS = (float*)(sm + OFF_BIAS);
    int*   gidxS = (int*)(sm + OFF_GIDX);
    float* maskS = (float*)(sm + OFF_MASK);

    // kick off Wi1' -> WL1; overlap with hx quantize
    prefetch_w(sb, OFF_WL1, 0, W1_BYTES);

    for (int i = tid; i < 512; i += THREADS) {
        const float* bp = (i < 128) ? i1b : (i < 256) ? i2b : (i < 384) ? j1b : j2b;
        biasS[i] = bp[i & 127];
    }
    if (tid < TILE_M) {
        int gn = blockIdx.x * TILE_M + tid;
        maskS[tid] = (gn < N) ? nmask[gn] : 0.0f;
        int lo = 0, hi = B - 1;
        while (lo < hi) {
            int mid = (lo + hi) >> 1;
            if (gn < g_cumsum[mid]) hi = mid; else lo = mid + 1;
        }
        gidxS[tid] = lo;
    }

    // ---- load + quantize x tile [64 x 64] f16 hi/lo; 4 threads per row ----
    {
        int m = tid & 63, q = tid >> 6;           // quarter q in 0..3 -> 16 floats
        int gn = blockIdx.x * TILE_M + m;
        char* hiB = sm + OFF_HX;
        char* loB = hiB + HX_HALF;
        float xv[16];
        if (gn < N) {
#pragma unroll
            for (int v4 = 0; v4 < 4; v4++)
                ((float4*)xv)[v4] = *(const float4*)&nodes[(size_t)gn * 64 + q * 16 + v4 * 4];
        } else {
#pragma unroll
            for (int i = 0; i < 16; i++) xv[i] = 0.0f;
        }
        uint32_t hw[8], lw[8];
#pragma unroll
        for (int p = 0; p < 8; p++)
            qsplit2(xv[2 * p], xv[2 * p + 1], hw[p], lw[p]);
        int base = m * (KST1 * 2) + q * 32;       // bytes, 16B aligned
#pragma unroll
        for (int v4 = 0; v4 < 2; v4++) {
            *(uint4*)(hiB + base + v4 * 16) = ((uint4*)hw)[v4];
            *(uint4*)(loB + base + v4 * 16) = ((uint4*)lw)[v4];
        }
    }

    uint32_t hxHi = sb + OFF_HX, hxLo = hxHi + HX_HALF;
    uint32_t acHi = sb + OFF_ACT, acLo = acHi + ACT_HALF;
    uint32_t wl1 = sb + OFF_WL1, wl2 = sb + OFF_WL2;

    CP_WAIT0();
    __syncthreads();

    float acc[2][4][4];
    float ri[2][4][4];   // i2 output (+bias) in registers

    // ===== G1: i layer-1 (WL1 = Wi1'); copy Wi2 -> WL2 underneath =====
    prefetch_w(sb, OFF_WL2, 1, W2_BYTES);
    zero_acc(acc);
    gemm_pass12<KSTEPS1, KST1>(hxHi, hxLo, wl1, acc, wm, wn, lane);
    epilogue_act<1>(acc, sm, 0, wm, wn, lane);
    CP_WAIT0(); __syncthreads();

    // ===== G2: i layer-2 (WL2 = Wi2) -> registers; copy Wj1' -> WL1 underneath =====
    prefetch_w(sb, OFF_WL1, 2, W1_BYTES);
    zero_acc(acc);
    gemm_pass12<KSTEPS2, KST2>(acHi, acLo, wl2, acc, wm, wn, lane);
    {
        const float* bias = biasS + 1 * 128;
#pragma unroll
        for (int nt = 0; nt < 4; nt++) {
            int n = wn * 32 + nt * 8 + 2 * (lane & 3);
            float2 bv = *(const float2*)&bias[n];
#pragma unroll
            for (int mt = 0; mt < 2; mt++) {
                ri[mt][nt][0] = acc[mt][nt][0] + bv.x;
                ri[mt][nt][1] = acc[mt][nt][1] + bv.y;
                ri[mt][nt][2] = acc[mt][nt][2] + bv.x;
                ri[mt][nt][3] = acc[mt][nt][3] + bv.y;
            }
        }
    }
    CP_WAIT0(); __syncthreads();

    // ===== G3: j layer-1 (WL1 = Wj1'); copy Wj2 -> WL2 underneath =====
    prefetch_w(sb, OFF_WL2, 3, W2_BYTES);
    zero_acc(acc);
    gemm_pass12<KSTEPS1, KST1>(hxHi, hxLo, wl1, acc, wm, wn, lane);
    epilogue_act<2>(acc, sm, 2, wm, wn, lane);   // G2 act reads finished at prior sync
    CP_WAIT0(); __syncthreads();

    // ===== G4: j layer-2 (WL2 = Wj2) =====
    zero_acc(acc);
    gemm_pass12<KSTEPS2, KST2>(acHi, acLo, wl2, acc, wm, wn, lane);
    __syncthreads();   // all act reads done before RR overlay

    // ---- gate: RR = sigmoid(i2) * (j2 + bias) * mask, overlay on ACT ----
    {
        const float* bias = biasS + 3 * 128;
        float* RR = (float*)(sm + OFF_ACT);
        int mb = wm * 32 + (lane >> 2);
#pragma unroll
        for (int nt = 0; nt < 4; nt++) {
            int n = wn * 32 + nt * 8 + 2 * (lane & 3);
            float2 bv = *(const float2*)&bias[n];
#pragma unroll
            for (int mt = 0; mt < 2; mt++)
#pragma unroll
                for (int half = 0; half < 2; half++) {
                    int m = mb + mt * 16 + half * 8;
                    float mk = maskS[m];
                    float2 o;
                    o.x = sigmoid_f(ri[mt][nt][2 * half])
                          * (acc[mt][nt][2 * half] + bv.x) * mk;
                    o.y = sigmoid_f(ri[mt][nt][2 * half + 1])
                          * (acc[mt][nt][2 * half + 1] + bv.y) * mk;
                    *(float2*)&RR[m * I2ST + n] = o;
                }
        }
    }
    __syncthreads();

    // ---- segmented column sum -> atomicAdd (2 threads per column, 32 rows each) ----
    {
        const float* RR = (const float*)(sm + OFF_ACT);
        int c = tid & 127;
        int h = tid >> 7;
        int m0 = h * 32;
        float cs = 0.0f;
        int gcur = gidxS[m0];
        for (int mm = m0; mm < m0 + 32; mm++) {
            float r = RR[mm * I2ST + c];
            int g = gidxS[mm];
            if (g != gcur) { atomicAdd(&g_pooled[gcur * RN + c], cs); cs = 0.0f; gcur = g; }
            cs += r;
        }
        atomicAdd(&g_pooled[gcur * RN + c], cs);
    }
}

// ============================ final per-graph MLP ============================
__global__ void final_kernel(const float* __restrict__ h1w, const float* __restrict__ h1b,
                             const float* __restrict__ h2w, const float* __restrict__ h2b,
                             float* __restrict__ out, int B) {
    int g = blockIdx.x * (blockDim.x >> 5) + (threadIdx.x >> 5);
    int lane = threadIdx.x & 31;
    if (g >= B) return;
    const float* pr = &g_pooled[g * RN];
    float4 bv = ((const float4*)h1b)[lane];
    float a0 = bv.x, a1 = bv.y, a2 = bv.z, a3 = bv.w;
#pragma unroll 4
    for (int k = 0; k < RN; k++) {
        float pv = pr[k];
        float4 wv = *(const float4*)(h1w + k * RN + (lane << 2));
        a0 = fmaf(pv, wv.x, a0);
        a1 = fmaf(pv, wv.y, a1);
        a2 = fmaf(pv, wv.z, a2);
        a3 = fmaf(pv, wv.w, a3);
    }
    a0 = selu_f(a0); a1 = selu_f(a1); a2 = selu_f(a2); a3 = selu_f(a3);
    float4 h2 = ((const float4*)h2w)[lane];
    float part = a0 * h2.x + a1 * h2.y + a2 * h2.z + a3 * h2.w;
#pragma unroll
    for (int off = 16; off > 0; off >>= 1)
        part += __shfl_down_sync(0xffffffffu, part, off);
    if (lane == 0) out[g] = part + h2b[0];
}

// ============================ launch ============================
extern "C" void kernel_launch(void* const* d_in, const int* in_sizes, int n_in,
                              void* d_out, int out_size) {
    const float* nodes = (const float*)d_in[0];
    const float* nmask = (const float*)d_in[1];
    const int*   n_node = (const int*)d_in[2];
    const float* i1w = (const float*)d_in[3];
    const float* i1b = (const float*)d_in[4];
    const float* i2w = (const float*)d_in[5];
    const float* i2b = (const float*)d_in[6];
    const float* j1w = (const float*)d_in[7];
    const float* j1b = (const float*)d_in[8];
    const float* j2w = (const float*)d_in[9];
    const float* j2b = (const float*)d_in[10];
    const float* h1w = (const float*)d_in[11];
    const float* h1b = (const float*)d_in[12];
    const float* h2w = (const float*)d_in[13];
    const float* h2b = (const float*)d_in[14];

    int N = in_sizes[1];
    int B = in_sizes[2];

    scan_kernel<<<1, 1024>>>(n_node, B);

    int pc = B * RN;
    zero_kernel<<<(pc + 255) / 256, 256>>>(pc);

    // layers: 0=i1' (K64, folded), 1=i2 (K128), 2=j1' (K64, folded), 3=j2 (K128)
    quant_w1_kernel<<<(128 * 64 + 255) / 256, 256>>>(i1w, 0);
    quant_w2_kernel<<<(128 * 128 + 255) / 256, 256>>>(i2w, 1);
    quant_w1_kernel<<<(128 * 64 + 255) / 256, 256>>>(j1w, 2);
    quant_w2_kernel<<<(128 * 128 + 255) / 256, 256>>>(j2w, 3);

    cudaFuncSetAttribute(fused_kernel, cudaFuncAttributeMaxDynamicSharedMemorySize, SMEM_SZ);
    int grid = (N + TILE_M - 1) / TILE_M;
    fused_kernel<<<grid, THREADS, SMEM_SZ>>>(nodes, nmask, i1b, i2b, j1b, j2b, N, B);

    final_kernel<<<(B + 7) / 8, 256>>>(h1w, h1b, h2w, h2b, (float*)d_out, B);
}

// round 8
// speedup vs baseline: 4.0603x; 1.0374x over previous
#include <cuda_runtime.h>
#include <cuda_fp16.h>
#include <cstdint>

// ============================ device scratch ============================
#define MAX_B 8192
__device__ float g_pooled[MAX_B * 128];
__device__ int   g_cumsum[MAX_B];
// f16 weight images Wt[n][k]: [layer][128*136]
__device__ __align__(16) __half g_wimg[4][128 * 136];

// ============================ constants ============================
#define RN       128
#define TILE_M   64
#define THREADS  256

#define KST1     72     // f16 stride, K=64 (144B rows, conflict-free ldsm)
#define KSTEPS1  4
#define KST2     136    // K=128 (272B rows)
#define KSTEPS2  8

#define HX_HALF  (TILE_M * KST1 * 2)          // 9216
#define OFF_HX   0                             // hi+lo = 18432
#define ACT_HALF (TILE_M * KST2 * 2)          // 17408
#define OFF_ACT  (2 * HX_HALF)                // 18432 ; hi+lo = 34816
#define W1_BYTES (128 * KST1 * 2)             // 18432
#define W2_BYTES (128 * KST2 * 2)             // 34816
#define OFF_WL1  (OFF_ACT + 2 * ACT_HALF)     // 53248
#define OFF_WL2  (OFF_WL1 + W1_BYTES)         // 71680
#define OFF_BIAS (OFF_WL2 + W2_BYTES)         // 106496 : 4*128 f32
#define OFF_GIDX (OFF_BIAS + 2048)            // 108544 : 64 ints
#define OFF_MASK (OFF_GIDX + 256)             // 108800 : 64 f32
#define SMEM_SZ  (OFF_MASK + 256)             // 109056  (x2 -> 2 CTAs/SM)

// ============================ ptx helpers ============================
__device__ __forceinline__ uint32_t smem_u32(const void* p) {
    uint32_t a;
    asm("{ .reg .u64 t; cvta.to.shared.u64 t, %1; cvt.u32.u64 %0, t; }" : "=r"(a) : "l"(p));
    return a;
}
__device__ __forceinline__ void ldsm4(uint32_t r[4], uint32_t a) {
    asm volatile("ldmatrix.sync.aligned.m8n8.x4.shared.b16 {%0,%1,%2,%3}, [%4];"
                 : "=r"(r[0]), "=r"(r[1]), "=r"(r[2]), "=r"(r[3]) : "r"(a));
}
__device__ __forceinline__ void mma16816(float c[4], const uint32_t a[4], uint32_t b0, uint32_t b1) {
    asm volatile(
        "mma.sync.aligned.m16n8k16.row.col.f32.f16.f16.f32 "
        "{%0,%1,%2,%3}, {%4,%5,%6,%7}, {%8,%9}, {%0,%1,%2,%3};"
        : "+f"(c[0]), "+f"(c[1]), "+f"(c[2]), "+f"(c[3])
        : "r"(a[0]), "r"(a[1]), "r"(a[2]), "r"(a[3]), "r"(b0), "r"(b1));
}
__device__ __forceinline__ void cp16(uint32_t dst, const void* src) {
    asm volatile("cp.async.cg.shared.global [%0], [%1], 16;" :: "r"(dst), "l"(src));
}
#define CP_COMMIT() asm volatile("cp.async.commit_group;" ::: "memory")
#define CP_WAIT0()  asm volatile("cp.async.wait_group 0;" ::: "memory")
#define CP_WAIT1()  asm volatile("cp.async.wait_group 1;" ::: "memory")

// ============================ math helpers ============================
__device__ __forceinline__ float fast_ex2(float x) { float r; asm("ex2.approx.ftz.f32 %0, %1;" : "=f"(r) : "f"(x)); return r; }
__device__ __forceinline__ float fast_rcp(float x) { float r; asm("rcp.approx.ftz.f32 %0, %1;" : "=f"(r) : "f"(x)); return r; }
#define L2E 1.4426950408889634f
__device__ __forceinline__ float sigmoid_f(float x) { return fast_rcp(1.0f + fast_ex2(-x * L2E)); }
__device__ __forceinline__ float tanh_f(float x)    { return 1.0f - 2.0f * fast_rcp(1.0f + fast_ex2(2.0f * x * L2E)); }
__device__ __forceinline__ float selu_f(float x) {
    float e = fast_ex2(x * L2E);
    float neg = 1.6732632423543772f * (e - 1.0f);
    return 1.0507009873554805f * ((x > 0.0f) ? x : neg);
}
__device__ __forceinline__ uint32_t pkh2(float e0, float e1) {
    uint32_t r; asm("cvt.rn.f16x2.f32 %0, %1, %2;" : "=r"(r) : "f"(e1), "f"(e0)); return r;
}
__device__ __forceinline__ void qsplit2(float e0, float e1, uint32_t& hw, uint32_t& lw) {
    hw = pkh2(e0, e1);
    float f0 = __half2float(__ushort_as_half((unsigned short)(hw & 0xffffu)));
    float f1 = __half2float(__ushort_as_half((unsigned short)(hw >> 16)));
    lw = pkh2(e0 - f0, e1 - f1);
}

// ============================ prologue kernels ============================
// scan of n_node + zero of g_pooled in one kernel (keeps fused_kernel at launch index 5)
__global__ void scan_zero_kernel(const int* __restrict__ nn, int B) {
    // zero pooled region
    int total4 = (B * RN) >> 2;
    float4 z = make_float4(0.0f, 0.0f, 0.0f, 0.0f);
    for (int i = threadIdx.x; i < total4; i += 1024)
        ((float4*)g_pooled)[i] = z;

    __shared__ int s[1024];
    int tid = threadIdx.x;
    int per = (B + 1023) >> 10;
    if (per > 8) per = 8;
    int base = tid * per;
    int loc[8];
    int sum = 0;
    for (int e = 0; e < per; e++) {
        int idx = base + e;
        int v = (idx < B) ? nn[idx] : 0;
        loc[e] = v; sum += v;
    }
    s[tid] = sum;
    __syncthreads();
    for (int off = 1; off < 1024; off <<= 1) {
        int v = (tid >= off) ? s[tid - off] : 0;
        __syncthreads();
        s[tid] += v;
        __syncthreads();
    }
    int run = s[tid] - sum;
    for (int e = 0; e < per; e++) {
        int idx = base + e;
        if (idx < B) { run += loc[e]; g_cumsum[idx] = run; }
    }
}

// layer-1 weights with exact coord fold: W'[k][n] = W[k][n] + (k<2 ? W[64+k][n] : 0), K=64
__global__ void quant_w1_kernel(const float* __restrict__ w, int layer) {
    int idx = blockIdx.x * blockDim.x + threadIdx.x;
    if (idx >= 128 * 64) return;
    int n = idx >> 6, k = idx & 63;
    float v = w[k * 128 + n];
    if (k < 2) v += w[(64 + k) * 128 + n];
    g_wimg[layer][n * KST1 + k] = __float2half(v);
}
__global__ void quant_w2_kernel(const float* __restrict__ w, int layer) {
    int idx = blockIdx.x * blockDim.x + threadIdx.x;
    if (idx >= 128 * 128) return;
    int n = idx >> 7, k = idx & 127;
    g_wimg[layer][n * KST2 + k] = __float2half(w[k * 128 + n]);
}

// ============================ gemm pieces ============================
__device__ __forceinline__ void prefetch_w(uint32_t sb, uint32_t dstOff, int layer, int bytes) {
    const char* src = (const char*)&g_wimg[layer][0];
    uint32_t dst = sb + dstOff;
    int n16 = bytes >> 4;
    for (int i = threadIdx.x; i < n16; i += THREADS)
        cp16(dst + (uint32_t)(i * 16), src + i * 16);
    CP_COMMIT();
}

__device__ __forceinline__ void zero_acc(float acc[2][4][4]) {
#pragma unroll
    for (int a = 0; a < 2; a++)
#pragma unroll
        for (int b = 0; b < 4; b++)
#pragma unroll
            for (int c = 0; c < 4; c++) acc[a][b][c] = 0.0f;
}

// merged 2-pass: (Ah + Al) * W, warp covers 32 rows x 32 cols
template <int KSTEPS, int KST>
__device__ __forceinline__ void gemm_pass12(uint32_t aHi, uint32_t aLo, uint32_t wBase,
                                            float acc[2][4][4], int wm, int wn, int lane) {
    uint32_t aOff = (uint32_t)(((wm * 32 + (lane & 15)) * KST + 8 * (lane >> 4)) * 2);
    uint32_t aH = aHi + aOff, aL = aLo + aOff;
    uint32_t bAddr = wBase + (uint32_t)(((wn * 32 + (lane & 7) + 8 * (lane >> 4)) * KST
                                         + 8 * ((lane >> 3) & 1)) * 2);
#pragma unroll
    for (int ks = 0; ks < KSTEPS; ks++) {
        uint32_t b[2][4];
#pragma unroll
        for (int g = 0; g < 2; g++) ldsm4(b[g], bAddr + g * (16 * KST * 2));
        bAddr += 32;
        uint32_t a0[4], a1[4];
        ldsm4(a0, aH); ldsm4(a1, aH + 16 * KST * 2); aH += 32;
#pragma unroll
        for (int g = 0; g < 2; g++) {
            mma16816(acc[0][2 * g],     a0, b[g][0], b[g][1]);
            mma16816(acc[0][2 * g + 1], a0, b[g][2], b[g][3]);
            mma16816(acc[1][2 * g],     a1, b[g][0], b[g][1]);
            mma16816(acc[1][2 * g + 1], a1, b[g][2], b[g][3]);
        }
        ldsm4(a0, aL); ldsm4(a1, aL + 16 * KST * 2); aL += 32;
#pragma unroll
        for (int g = 0; g < 2; g++) {
            mma16816(acc[0][2 * g],     a0, b[g][0], b[g][1]);
            mma16816(acc[0][2 * g + 1], a0, b[g][2], b[g][3]);
            mma16816(acc[1][2 * g],     a1, b[g][0], b[g][1]);
            mma16816(acc[1][2 * g + 1], a1, b[g][2], b[g][3]);
        }
    }
}

// ACT 1 = tanh, 2 = selu
template <int ACT>
__device__ __forceinline__ void epilogue_act(float acc[2][4][4], char* sm, int biasIdx,
                                             int wm, int wn, int lane) {
    const float* bias = (const float*)(sm + OFF_BIAS) + biasIdx * 128;
    char* hiB = sm + OFF_ACT;
    char* loB = hiB + ACT_HALF;
    int mb = wm * 32 + (lane >> 2);
#pragma unroll
    for (int nt = 0; nt < 4; nt++) {
        int n = wn * 32 + nt * 8 + 2 * (lane & 3);
        float2 bv = *(const float2*)&bias[n];
#pragma unroll
        for (int mt = 0; mt < 2; mt++)
#pragma unroll
            for (int half = 0; half < 2; half++) {
                int m = mb + mt * 16 + half * 8;
                float x0 = acc[mt][nt][2 * half]     + bv.x;
                float x1 = acc[mt][nt][2 * half + 1] + bv.y;
                x0 = (ACT == 1) ? tanh_f(x0) : selu_f(x0);
                x1 = (ACT == 1) ? tanh_f(x1) : selu_f(x1);
                uint32_t hw, lw;
                qsplit2(x0, x1, hw, lw);
                int off = (m * KST2 + n) * 2;
                *(uint32_t*)(hiB + off) = hw;
                *(uint32_t*)(loB + off) = lw;
            }
    }
}

// ============================ fused main kernel ============================
__global__ void __launch_bounds__(THREADS, 2)
fused_kernel(const float* __restrict__ nodes, const float* __restrict__ nmask,
             const float* __restrict__ i1b, const float* __restrict__ i2b,
             const float* __restrict__ j1b, const float* __restrict__ j2b,
             int N, int B) {
    extern __shared__ char sm[];
    uint32_t sb = smem_u32(sm);
    int tid = threadIdx.x;
    int lane = tid & 31, wid = tid >> 5;
    int wm = wid & 1, wn = wid >> 1;     // 2 x 4 warp grid: 32 rows x 32 cols each

    float* biasS = (float*)(sm + OFF_BIAS);
    int*   gidxS = (int*)(sm + OFF_GIDX);
    float* maskS = (float*)(sm + OFF_MASK);

    // kick off BOTH first-phase weight copies immediately (2 commit groups)
    prefetch_w(sb, OFF_WL1, 0, W1_BYTES);   // Wi1' (group A)
    prefetch_w(sb, OFF_WL2, 1, W2_BYTES);   // Wi2  (group B)

    for (int i = tid; i < 512; i += THREADS) {
        const float* bp = (i < 128) ? i1b : (i < 256) ? i2b : (i < 384) ? j1b : j2b;
        biasS[i] = bp[i & 127];
    }
    if (tid < TILE_M) {
        int gn = blockIdx.x * TILE_M + tid;
        maskS[tid] = (gn < N) ? nmask[gn] : 0.0f;
        int lo = 0, hi = B - 1;
        while (lo < hi) {
            int mid = (lo + hi) >> 1;
            if (gn < g_cumsum[mid]) hi = mid; else lo = mid + 1;
        }
        gidxS[tid] = lo;
    }

    // ---- load + quantize x tile [64 x 64] f16 hi/lo; 4 threads per row ----
    {
        int m = tid & 63, q = tid >> 6;
        int gn = blockIdx.x * TILE_M + m;
        char* hiB = sm + OFF_HX;
        char* loB = hiB + HX_HALF;
        float xv[16];
        if (gn < N) {
#pragma unroll
            for (int v4 = 0; v4 < 4; v4++)
                ((float4*)xv)[v4] = *(const float4*)&nodes[(size_t)gn * 64 + q * 16 + v4 * 4];
        } else {
#pragma unroll
            for (int i = 0; i < 16; i++) xv[i] = 0.0f;
        }
        uint32_t hw[8], lw[8];
#pragma unroll
        for (int p = 0; p < 8; p++)
            qsplit2(xv[2 * p], xv[2 * p + 1], hw[p], lw[p]);
        int base = m * (KST1 * 2) + q * 32;
#pragma unroll
        for (int v4 = 0; v4 < 2; v4++) {
            *(uint4*)(hiB + base + v4 * 16) = ((uint4*)hw)[v4];
            *(uint4*)(loB + base + v4 * 16) = ((uint4*)lw)[v4];
        }
    }

    uint32_t hxHi = sb + OFF_HX, hxLo = hxHi + HX_HALF;
    uint32_t acHi = sb + OFF_ACT, acLo = acHi + ACT_HALF;
    uint32_t wl1 = sb + OFF_WL1, wl2 = sb + OFF_WL2;

    CP_WAIT1();          // Wi1' done (Wi2 may still be in flight)
    __syncthreads();

    float acc[2][4][4];
    float ri[2][4][4];   // i2 output (+bias) in registers

    // ===== G1: i layer-1 (WL1 = Wi1') =====
    zero_acc(acc);
    gemm_pass12<KSTEPS1, KST1>(hxHi, hxLo, wl1, acc, wm, wn, lane);
    epilogue_act<1>(acc, sm, 0, wm, wn, lane);
    CP_WAIT0();          // Wi2 done
    __syncthreads();

    // ===== G2: i layer-2 (WL2 = Wi2) -> registers; copy Wj1' -> WL1 underneath =====
    prefetch_w(sb, OFF_WL1, 2, W1_BYTES);
    zero_acc(acc);
    gemm_pass12<KSTEPS2, KST2>(acHi, acLo, wl2, acc, wm, wn, lane);
    {
        const float* bias = biasS + 1 * 128;
#pragma unroll
        for (int nt = 0; nt < 4; nt++) {
            int n = wn * 32 + nt * 8 + 2 * (lane & 3);
            float2 bv = *(const float2*)&bias[n];
#pragma unroll
            for (int mt = 0; mt < 2; mt++) {
                ri[mt][nt][0] = acc[mt][nt][0] + bv.x;
                ri[mt][nt][1] = acc[mt][nt][1] + bv.y;
                ri[mt][nt][2] = acc[mt][nt][2] + bv.x;
                ri[mt][nt][3] = acc[mt][nt][3] + bv.y;
            }
        }
    }
    CP_WAIT0(); __syncthreads();

    // ===== G3: j layer-1 (WL1 = Wj1'); copy Wj2 -> WL2 underneath =====
    prefetch_w(sb, OFF_WL2, 3, W2_BYTES);
    zero_acc(acc);
    gemm_pass12<KSTEPS1, KST1>(hxHi, hxLo, wl1, acc, wm, wn, lane);
    epilogue_act<2>(acc, sm, 2, wm, wn, lane);   // G2's act reads finished at prior sync
    CP_WAIT0(); __syncthreads();

    // ===== G4: j layer-2 (WL2 = Wj2) =====
    zero_acc(acc);
    gemm_pass12<KSTEPS2, KST2>(acHi, acLo, wl2, acc, wm, wn, lane);

    // ===== gate + pooled reduction, register path (no smem, no trailing syncs) =====
    {
        const float* bias = biasS + 3 * 128;
        int r0 = wm * 32;
        bool uniform = (gidxS[r0] == gidxS[r0 + 31]);   // warp-uniform
        int baseRow = r0 + (lane >> 2);
        float mk[2][2];
#pragma unroll
        for (int mt = 0; mt < 2; mt++)
#pragma unroll
            for (int half = 0; half < 2; half++)
                mk[mt][half] = maskS[baseRow + mt * 16 + half * 8];

        if (uniform) {
            int g = gidxS[r0];
#pragma unroll
            for (int nt = 0; nt < 4; nt++) {
                int n = wn * 32 + nt * 8 + 2 * (lane & 3);
                float2 bv = *(const float2*)&bias[n];
                float s0 = 0.0f, s1 = 0.0f;
#pragma unroll
                for (int mt = 0; mt < 2; mt++)
#pragma unroll
                    for (int half = 0; half < 2; half++) {
                        s0 += sigmoid_f(ri[mt][nt][2 * half])
                              * (acc[mt][nt][2 * half] + bv.x) * mk[mt][half];
                        s1 += sigmoid_f(ri[mt][nt][2 * half + 1])
                              * (acc[mt][nt][2 * half + 1] + bv.y) * mk[mt][half];
                    }
#pragma unroll
                for (int st = 4; st <= 16; st <<= 1) {
                    s0 += __shfl_xor_sync(0xffffffffu, s0, st);
                    s1 += __shfl_xor_sync(0xffffffffu, s1, st);
                }
                if ((lane >> 2) == 0) {
                    int nc = wn * 32 + nt * 8 + 2 * lane;   // lane in 0..3
                    atomicAdd(&g_pooled[g * RN + nc], s0);
                    atomicAdd(&g_pooled[g * RN + nc + 1], s1);
                }
            }
        } else {
            // boundary warp (rare): per-value reduction
#pragma unroll
            for (int nt = 0; nt < 4; nt++) {
                int n = wn * 32 + nt * 8 + 2 * (lane & 3);
                float2 bv = *(const float2*)&bias[n];
#pragma unroll
                for (int mt = 0; mt < 2; mt++)
#pragma unroll
                    for (int half = 0; half < 2; half++) {
                        int r = baseRow + mt * 16 + half * 8;
                        int g = gidxS[r];
                        float v0 = sigmoid_f(ri[mt][nt][2 * half])
                                   * (acc[mt][nt][2 * half] + bv.x) * mk[mt][half];
                        float v1 = sigmoid_f(ri[mt][nt][2 * half + 1])
                                   * (acc[mt][nt][2 * half + 1] + bv.y) * mk[mt][half];
                        atomicAdd(&g_pooled[g * RN + n], v0);
                        atomicAdd(&g_pooled[g * RN + n + 1], v1);
                    }
            }
        }
    }
    // CTA done — no trailing syncs
}

// ============================ final per-graph MLP ============================
__global__ void final_kernel(const float* __restrict__ h1w, const float* __restrict__ h1b,
                             const float* __restrict__ h2w, const float* __restrict__ h2b,
                             float* __restrict__ out, int B) {
    int g = blockIdx.x * (blockDim.x >> 5) + (threadIdx.x >> 5);
    int lane = threadIdx.x & 31;
    if (g >= B) return;
    const float* pr = &g_pooled[g * RN];
    float4 bv = ((const float4*)h1b)[lane];
    float a0 = bv.x, a1 = bv.y, a2 = bv.z, a3 = bv.w;
#pragma unroll 4
    for (int k = 0; k < RN; k++) {
        float pv = pr[k];
        float4 wv = *(const float4*)(h1w + k * RN + (lane << 2));
        a0 = fmaf(pv, wv.x, a0);
        a1 = fmaf(pv, wv.y, a1);
        a2 = fmaf(pv, wv.z, a2);
        a3 = fmaf(pv, wv.w, a3);
    }
    a0 = selu_f(a0); a1 = selu_f(a1); a2 = selu_f(a2); a3 = selu_f(a3);
    float4 h2 = ((const float4*)h2w)[lane];
    float part = a0 * h2.x + a1 * h2.y + a2 * h2.z + a3 * h2.w;
#pragma unroll
    for (int off = 16; off > 0; off >>= 1)
        part += __shfl_down_sync(0xffffffffu, part, off);
    if (lane == 0) out[g] = part + h2b[0];
}

// ============================ launch ============================
extern "C" void kernel_launch(void* const* d_in, const int* in_sizes, int n_in,
                              void* d_out, int out_size) {
    const float* nodes = (const float*)d_in[0];
    const float* nmask = (const float*)d_in[1];
    const int*   n_node = (const int*)d_in[2];
    const float* i1w = (const float*)d_in[3];
    const float* i1b = (const float*)d_in[4];
    const float* i2w = (const float*)d_in[5];
    const float* i2b = (const float*)d_in[6];
    const float* j1w = (const float*)d_in[7];
    const float* j1b = (const float*)d_in[8];
    const float* j2w = (const float*)d_in[9];
    const float* j2b = (const float*)d_in[10];
    const float* h1w = (const float*)d_in[11];
    const float* h1b = (const float*)d_in[12];
    const float* h2w = (const float*)d_in[13];
    const float* h2b = (const float*)d_in[14];

    int N = in_sizes[1];
    int B = in_sizes[2];

    // launch order keeps fused_kernel at index 5 (ncu -s 5 -c 1 profiles it)
    scan_zero_kernel<<<1, 1024>>>(n_node, B);                            // 0
    quant_w1_kernel<<<(128 * 64 + 255) / 256, 256>>>(i1w, 0);            // 1
    quant_w2_kernel<<<(128 * 128 + 255) / 256, 256>>>(i2w, 1);           // 2
    quant_w1_kernel<<<(128 * 64 + 255) / 256, 256>>>(j1w, 2);            // 3
    quant_w2_kernel<<<(128 * 128 + 255) / 256, 256>>>(j2w, 3);           // 4

    cudaFuncSetAttribute(fused_kernel, cudaFuncAttributeMaxDynamicSharedMemorySize, SMEM_SZ);
    int grid = (N + TILE_M - 1) / TILE_M;
    fused_kernel<<<grid, THREADS, SMEM_SZ>>>(nodes, nmask, i1b, i2b, j1b, j2b, N, B);  // 5

    final_kernel<<<(B + 7) / 8, 256>>>(h1w, h1b, h2w, h2b, (float*)d_out, B);          // 6
}